// round 8
// baseline (speedup 1.0000x reference)
#include <cuda_runtime.h>

// ============================================================================
// Problem constants
// ============================================================================
#define NFEAT 32
#define MAX_ATOMS 10000
#define NPATHS 19

// Scratch: per-atom B = A @ W1   (10000 * 9 * 32 floats)
__device__ float g_B[MAX_ATOMS * 9 * NFEAT];

// ============================================================================
// constexpr Clebsch-Gordan machinery — bit-faithful port of the reference
// (_cg_complex, _U, _real_cg), evaluated at COMPILE TIME so every coefficient
// becomes an FFMA immediate in SASS.
// ============================================================================
__host__ __device__ constexpr double cfact(int n) {
    double r = 1.0;
    for (int i = 2; i <= n; ++i) r *= (double)i;
    return r;
}
__host__ __device__ constexpr double csqrt_(double x) {
    if (x <= 0.0) return 0.0;
    double g = x < 1.0 ? 1.0 : x;
    for (int i = 0; i < 80; ++i) g = 0.5 * (g + x / g);
    return g;
}
__host__ __device__ constexpr int iabs_(int x) { return x < 0 ? -x : x; }

__host__ __device__ constexpr double cg_c(int j1, int m1, int j2, int m2, int j3, int m3) {
    if (m1 + m2 != m3) return 0.0;
    if (j3 < iabs_(j1 - j2) || j3 > j1 + j2) return 0.0;
    if (iabs_(m1) > j1 || iabs_(m2) > j2 || iabs_(m3) > j3) return 0.0;
    double pref = csqrt_((2.0 * j3 + 1.0) * cfact(j3 + j1 - j2) * cfact(j3 - j1 + j2) *
                         cfact(j1 + j2 - j3) / cfact(j1 + j2 + j3 + 1));
    pref *= csqrt_(cfact(j3 + m3) * cfact(j3 - m3) * cfact(j1 - m1) * cfact(j1 + m1) *
                   cfact(j2 - m2) * cfact(j2 + m2));
    double s = 0.0;
    for (int k = 0; k <= j1 + j2 - j3; ++k) {
        int d1 = j1 + j2 - j3 - k, d2 = j1 - m1 - k, d3 = j2 + m2 - k;
        int d4 = j3 - j2 + m1 + k, d5 = j3 - j1 - m2 + k;
        if (d1 < 0 || d2 < 0 || d3 < 0 || d4 < 0 || d5 < 0) continue;
        double den = cfact(k) * cfact(d1) * cfact(d2) * cfact(d3) * cfact(d4) * cfact(d5);
        s += ((k & 1) ? -1.0 : 1.0) / den;
    }
    return pref * s;
}

struct CPX { double re, im; };
__host__ __device__ constexpr CPX cmulc(CPX a, CPX b) {
    return CPX{a.re * b.re - a.im * b.im, a.re * b.im + a.im * b.re};
}
__host__ __device__ constexpr CPX Uent(int l, int mr, int mc) {
    (void)l;
    double is2 = 1.0 / csqrt_(2.0);
    if (mr > 0) {
        if (mc == mr)  return CPX{((mr & 1) ? -1.0 : 1.0) * is2, 0.0};
        if (mc == -mr) return CPX{is2, 0.0};
    } else if (mr == 0) {
        if (mc == 0) return CPX{1.0, 0.0};
    } else {
        int mu = -mr;
        if (mc == mr) return CPX{0.0, is2};
        if (mc == mu) return CPX{0.0, -((mu & 1) ? -1.0 : 1.0) * is2};
    }
    return CPX{0.0, 0.0};
}

__host__ __device__ constexpr double real_cg(int l1, int l2, int l3, int a, int b, int c) {
    int m1 = a - l1, m2 = b - l2, m3 = c - l3;
    double re = 0.0, im = 0.0;
    for (int sx = 0; sx < 2; ++sx) {
        if (sx && m1 == 0) continue;
        int x = sx ? -m1 : m1;
        CPX u1 = Uent(l1, m1, x); u1.im = -u1.im;
        for (int sy = 0; sy < 2; ++sy) {
            if (sy && m2 == 0) continue;
            int y = sy ? -m2 : m2;
            CPX u2 = Uent(l2, m2, y); u2.im = -u2.im;
            for (int sz = 0; sz < 2; ++sz) {
                if (sz && m3 == 0) continue;
                int z = sz ? -m3 : m3;
                CPX u3 = Uent(l3, m3, z);
                double cg = cg_c(l1, x, l2, y, l3, z);
                if (cg == 0.0) continue;
                CPX t = cmulc(cmulc(u1, u2), u3);
                re += t.re * cg;
                im += t.im * cg;
            }
        }
    }
    return ((l1 + l2 + l3) & 1) ? im : re;
}

// Path table, same enumeration order as reference _build_paths()
__host__ __device__ constexpr int PL1[NPATHS] = {0,0,0,1,1,1,1,1,1,1,2,2,2,2,2,2,2,2,2};
__host__ __device__ constexpr int PL2[NPATHS] = {0,1,2,0,1,1,1,2,2,2,0,1,1,1,2,2,2,2,2};
__host__ __device__ constexpr int PL3[NPATHS] = {0,1,2,1,0,1,2,1,2,3,2,1,2,3,0,1,2,3,4};

// Flat accumulator layout: par0 l3=0..4 at c=l3*l3 (25 slots),
// par1 l3=1..3 at 25 + (l3*l3 - 1)  (15 slots) -> 40 total
__host__ __device__ constexpr int blk_off(int par, int l3) {
    return par == 0 ? l3 * l3 : 25 + (l3 * l3 - 1);
}

template <int I> struct IC { static constexpr int v = I; };
template <int I, int N, class F>
__device__ __forceinline__ void sfor(F&& f) {
    if constexpr (I < N) {
        f(IC<I>{});
        sfor<I + 1, N>(f);
    }
}

__device__ __forceinline__ float wsum(float v) {
    v += __shfl_xor_sync(0xffffffffu, v, 16);
    v += __shfl_xor_sync(0xffffffffu, v, 8);
    v += __shfl_xor_sync(0xffffffffu, v, 4);
    v += __shfl_xor_sync(0xffffffffu, v, 2);
    v += __shfl_xor_sync(0xffffffffu, v, 1);
    return v;
}

// packed f32x2 fma (sm_103): acc = a*b + acc, lanes independent
__device__ __forceinline__ void ffma2(unsigned long long& acc,
                                      unsigned long long a, unsigned long long b) {
    asm("fma.rn.f32x2 %0, %1, %2, %0;" : "+l"(acc) : "l"(a), "l"(b));
}
__device__ __forceinline__ unsigned long long pk2(float lo, float hi) {
    unsigned long long r;
    asm("mov.b64 %0, {%1, %2};" : "=l"(r) : "f"(lo), "f"(hi));
    return r;
}
__device__ __forceinline__ float upk_sum(unsigned long long v) {
    float lo, hi;
    asm("mov.b64 {%0, %1}, %2;" : "=f"(lo), "=f"(hi) : "l"(v));
    return lo + hi;
}

// ============================================================================
// Kernel 1: per-atom B = A @ W1.  warp = row, W1 column resident in registers.
// ============================================================================
__global__ void __launch_bounds__(128) atom_dense_kernel(
    const float* __restrict__ A, const float* __restrict__ W1, int n_rows) {
    const int lane = threadIdx.x & 31;
    float wcol[32];
#pragma unroll
    for (int g = 0; g < 32; ++g) wcol[g] = W1[g * 32 + lane];
    const int wid = (blockIdx.x * blockDim.x + threadIdx.x) >> 5;
    const int nw = (gridDim.x * blockDim.x) >> 5;
    for (int row = wid; row < n_rows; row += nw) {
        const float4* ar = (const float4*)(A + (size_t)row * 32);
        float acc = 0.f;
#pragma unroll
        for (int q = 0; q < 8; ++q) {
            float4 v = ar[q];
            acc = fmaf(v.x, wcol[4 * q + 0], acc);
            acc = fmaf(v.y, wcol[4 * q + 1], acc);
            acc = fmaf(v.z, wcol[4 * q + 2], acc);
            acc = fmaf(v.w, wcol[4 * q + 3], acc);
        }
        g_B[(size_t)row * 32 + lane] = acc;
    }
}

// ============================================================================
// Kernel 2: fused per-edge pipeline. warp = edge, lane = feature.
// ============================================================================
__global__ void __launch_bounds__(128, 3) edge_kernel(
    const int* __restrict__ nbr, const float* __restrict__ disp,
    const float* __restrict__ b1, const float* __restrict__ lng,
    const float* __restrict__ lnb, const float* __restrict__ W2,
    const float* __restrict__ b2, const float* __restrict__ Wb,
    const float* __restrict__ bbv, const float* __restrict__ tpw_g,
    float* __restrict__ out, int E) {
    __shared__ __align__(16) float s_wb[1024];         // Wb[k][g]
    __shared__ __align__(16) float s_tpw[NPATHS * 32]; // tp_w[p][g]
    __shared__ __align__(16) float s_yg[4][9][32];     // per-warp gated features

    const int lane = threadIdx.x & 31;
    const int wib = threadIdx.x >> 5;

    for (int x = threadIdx.x; x < 1024; x += blockDim.x) s_wb[x] = Wb[x];
    for (int x = threadIdx.x; x < NPATHS * 32; x += blockDim.x) s_tpw[x] = tpw_g[x];
    __syncthreads();

    // W2 column for this lane, packed into f32x2 pairs (features 2k,2k+1)
    unsigned long long w2p[16];
#pragma unroll
    for (int k = 0; k < 16; ++k)
        w2p[k] = pk2(W2[(2 * k) * 32 + lane], W2[(2 * k + 1) * 32 + lane]);

    const float b1v = b1[lane], b2v = b2[lane], bbc = bbv[lane], betav = lnb[lane];
    const float gm0 = lng[lane], gm1 = lng[32 + lane], gm2 = lng[64 + lane];

    const int wid = (blockIdx.x * blockDim.x + threadIdx.x) >> 5;
    const int nw = (gridDim.x * blockDim.x) >> 5;
    const int2* __restrict__ nbr2 = (const int2*)nbr;

    for (int e = wid; e < E; e += nw) {
        const int2 ij = nbr2[e];

        // ---- y0 = B[i] + B[j] (+ b1 on scalar channel) ----
        float y0[9];
#pragma unroll
        for (int m = 0; m < 9; ++m)
            y0[m] = g_B[((size_t)ij.x * 9 + m) * 32 + lane] +
                    g_B[((size_t)ij.y * 9 + m) * 32 + lane];
        y0[0] += b1v;

        // ---- equivariant layernorm ----
        float yg[9];
        {
            float s = y0[0];
            float mu = wsum(s) * (1.f / 32.f);
            float d = s - mu;
            float var = wsum(d * d) * (1.f / 32.f);
            yg[0] = d * rsqrtf(var + 1e-6f) * gm0 + betav;

            float ss1 = y0[1] * y0[1] + y0[2] * y0[2] + y0[3] * y0[3];
            float inv1 = gm1 * rsqrtf(wsum(ss1) * (1.f / 96.f) + 1e-6f);
            yg[1] = y0[1] * inv1; yg[2] = y0[2] * inv1; yg[3] = y0[3] * inv1;

            float ss2 = y0[4] * y0[4] + y0[5] * y0[5] + y0[6] * y0[6] +
                        y0[7] * y0[7] + y0[8] * y0[8];
            float inv2 = gm2 * rsqrtf(wsum(ss2) * (1.f / 160.f) + 1e-6f);
#pragma unroll
            for (int m = 4; m < 9; ++m) yg[m] = y0[m] * inv2;
        }

        // ---- mish gate (fast-math) ----
        {
            float s = yg[0];
            float ea = __expf(-fabsf(s));
            float sp = fmaxf(s, 0.f) + __logf(1.f + ea);
            float E2 = __expf(-2.f * sp);
            float th = __fdividef(1.f - E2, 1.f + E2);
            float i1 = __fdividef(1.f, 1.f + ea);
            float sig = (s >= 0.f) ? i1 : 1.f - i1;
            yg[0] = s * th;
            float dg = th + s * (1.f - th * th) * sig;
#pragma unroll
            for (int m = 1; m < 9; ++m) yg[m] *= dg;
        }

        // ---- bond geometry + windowed radial contraction ----
        // rad_k = exp(-20.48*(r-ck)^2): sigma=0.156, spacing=0.1613 -> terms
        // beyond +-7 bins are < 5e-12; truncate (cut factored out of linear sum).
        float dx = disp[3 * e], dy = disp[3 * e + 1], dz = disp[3 * e + 2];
        float r = sqrtf(dx * dx + dy * dy + dz * dz);
        float rinv = __fdividef(1.f, fmaxf(r, 1e-12f));
        float ux = dx * rinv, uy = dy * rinv, uz = dz * rinv;

        float radW = 0.f;
        if (r < 5.f) {                              // warp-uniform branch
            int kc = __float2int_rn(r * (31.0f / 5.0f));
            int klo = kc - 7 < 0 ? 0 : kc - 7;
            int khi = kc + 7 > 31 ? 31 : kc + 7;
            for (int k = klo; k <= khi; ++k) {
                float dr = r - (float)k * (5.0f / 31.0f);
                float g = __expf(-20.48f * dr * dr);
                radW = fmaf(g, s_wb[(k << 5) + lane], radW);
            }
            float cut = 0.5f * (__cosf(r * 0.6283185307179586f) + 1.f);
            radW *= cut;
        }

        const float s3 = 1.7320508075688772f;
        float av[9];
        av[0] = radW + bbc;
        av[1] = uy * radW; av[2] = uz * radW; av[3] = ux * radW;
        av[4] = s3 * ux * uy * radW;
        av[5] = s3 * uy * uz * radW;
        av[6] = 0.5f * (3.f * uz * uz - 1.f) * radW;
        av[7] = s3 * ux * uz * radW;
        av[8] = 0.5f * s3 * (ux * ux - uy * uy) * radW;

        // ---- stage yg to smem for broadcast dense2 ----
        __syncwarp();
#pragma unroll
        for (int m = 0; m < 9; ++m) s_yg[wib][m][lane] = yg[m];
        __syncwarp();

        // ---- dense2 via uniform LDS.128 + packed f32x2 FMA ----
        float y2[9];
        {
            const ulonglong2* yq = (const ulonglong2*)&s_yg[wib][0][0];
            sfor<0, 9>([&](auto M) {
                constexpr int m = decltype(M)::v;
                unsigned long long acc = 0ull;
#pragma unroll
                for (int q = 0; q < 8; ++q) {
                    ulonglong2 v = yq[m * 8 + q];   // yg[m][4q..4q+3]
                    ffma2(acc, v.x, w2p[2 * q]);
                    ffma2(acc, v.y, w2p[2 * q + 1]);
                }
                y2[m] = upk_sum(acc);
            });
        }
        y2[0] += b2v;
#pragma unroll
        for (int m = 0; m < 9; ++m) y2[m] += y0[m];

        // ---- tensor product: group-factored (share q = av⊗y2 across l3) ----
        float ACC[40] = {};

        auto do_group = [&](auto L1c, auto L2c) {
            constexpr int l1 = decltype(L1c)::v, l2 = decltype(L2c)::v;
            constexpr int NA = 2 * l1 + 1, NB = 2 * l2 + 1;
            float q[NA * NB];
            sfor<0, NA>([&](auto A) {
                sfor<0, NB>([&](auto B) {
                    q[decltype(A)::v * NB + decltype(B)::v] =
                        av[l1 * l1 + decltype(A)::v] * y2[l2 * l2 + decltype(B)::v];
                });
            });
            sfor<0, NPATHS>([&](auto P) {
                constexpr int p = decltype(P)::v;
                if constexpr (PL1[p] == l1 && PL2[p] == l2) {
                    constexpr int l3 = PL3[p];
                    constexpr int par = (l1 + l2 + l3) & 1;
                    constexpr int off = blk_off(par, l3);
                    float u[2 * l3 + 1];
                    sfor<0, 2 * l3 + 1>([&](auto C) { u[decltype(C)::v] = 0.f; });
                    sfor<0, NA>([&](auto A) {
                        sfor<0, NB>([&](auto B) {
                            sfor<0, 2 * l3 + 1>([&](auto C) {
                                constexpr float cf = (float)real_cg(
                                    l1, l2, l3, decltype(A)::v, decltype(B)::v, decltype(C)::v);
                                if constexpr (cf > 1e-7f || cf < -1e-7f)
                                    u[decltype(C)::v] = fmaf(
                                        cf, q[decltype(A)::v * NB + decltype(B)::v],
                                        u[decltype(C)::v]);
                            });
                        });
                    });
                    float tw = s_tpw[p * 32 + lane];
                    sfor<0, 2 * l3 + 1>([&](auto C) {
                        ACC[off + decltype(C)::v] =
                            fmaf(tw, u[decltype(C)::v], ACC[off + decltype(C)::v]);
                    });
                }
            });
        };

        do_group(IC<0>{}, IC<0>{});
        do_group(IC<0>{}, IC<1>{});
        do_group(IC<0>{}, IC<2>{});
        do_group(IC<1>{}, IC<0>{});
        do_group(IC<1>{}, IC<1>{});
        do_group(IC<1>{}, IC<2>{});
        do_group(IC<2>{}, IC<0>{});
        do_group(IC<2>{}, IC<1>{});
        do_group(IC<2>{}, IC<2>{});

        // ---- store (E, 2, 25, 32) ----
        float* ob = out + (size_t)e * 1600 + lane;
        sfor<0, 25>([&](auto C) { ob[decltype(C)::v * 32] = ACC[decltype(C)::v]; });
        ob[25 * 32] = 0.f;                                  // par1 l3=0: zero
        sfor<0, 15>([&](auto C) {                           // par1 l3=1..3 -> c=1..15
            ob[(26 + decltype(C)::v) * 32] = ACC[25 + decltype(C)::v];
        });
        sfor<16, 25>([&](auto C) {                          // par1 l3=4: zero
            ob[(25 + decltype(C)::v) * 32] = 0.f;
        });
    }
}

// ============================================================================
// Launch
// ============================================================================
extern "C" void kernel_launch(void* const* d_in, const int* in_sizes, int n_in,
                              void* d_out, int out_size) {
    const float* A    = (const float*)d_in[0];
    const int*   nbr  = (const int*)d_in[1];
    const float* disp = (const float*)d_in[2];
    const float* W1   = (const float*)d_in[3];
    const float* b1   = (const float*)d_in[4];
    const float* lng  = (const float*)d_in[5];
    const float* lnb  = (const float*)d_in[6];
    const float* W2   = (const float*)d_in[7];
    const float* b2   = (const float*)d_in[8];
    const float* Wb   = (const float*)d_in[9];
    const float* bb   = (const float*)d_in[10];
    const float* tpw  = (const float*)d_in[11];
    float* out = (float*)d_out;

    int n_atoms = in_sizes[0] / (9 * NFEAT);
    int E = in_sizes[1] / 2;

    atom_dense_kernel<<<592, 128>>>(A, W1, n_atoms * 9);
    edge_kernel<<<444, 128>>>(nbr, disp, b1, lng, lnb, W2, b2, Wb, bb, tpw, out, E);
    (void)n_in; (void)out_size;
}

// round 9
// speedup vs baseline: 1.1552x; 1.1552x over previous
#include <cuda_runtime.h>

// ============================================================================
// Problem constants
// ============================================================================
#define NFEAT 32
#define MAX_ATOMS 10000
#define NPATHS 19

// Scratch: per-atom B = A @ W1   (10000 * 9 * 32 floats)
__device__ float g_B[MAX_ATOMS * 9 * NFEAT];

// ============================================================================
// constexpr Clebsch-Gordan machinery — bit-faithful port of the reference
// (_cg_complex, _U, _real_cg), evaluated at COMPILE TIME so every coefficient
// becomes an FFMA immediate in SASS.
// ============================================================================
__host__ __device__ constexpr double cfact(int n) {
    double r = 1.0;
    for (int i = 2; i <= n; ++i) r *= (double)i;
    return r;
}
__host__ __device__ constexpr double csqrt_(double x) {
    if (x <= 0.0) return 0.0;
    double g = x < 1.0 ? 1.0 : x;
    for (int i = 0; i < 80; ++i) g = 0.5 * (g + x / g);
    return g;
}
__host__ __device__ constexpr int iabs_(int x) { return x < 0 ? -x : x; }

__host__ __device__ constexpr double cg_c(int j1, int m1, int j2, int m2, int j3, int m3) {
    if (m1 + m2 != m3) return 0.0;
    if (j3 < iabs_(j1 - j2) || j3 > j1 + j2) return 0.0;
    if (iabs_(m1) > j1 || iabs_(m2) > j2 || iabs_(m3) > j3) return 0.0;
    double pref = csqrt_((2.0 * j3 + 1.0) * cfact(j3 + j1 - j2) * cfact(j3 - j1 + j2) *
                         cfact(j1 + j2 - j3) / cfact(j1 + j2 + j3 + 1));
    pref *= csqrt_(cfact(j3 + m3) * cfact(j3 - m3) * cfact(j1 - m1) * cfact(j1 + m1) *
                   cfact(j2 - m2) * cfact(j2 + m2));
    double s = 0.0;
    for (int k = 0; k <= j1 + j2 - j3; ++k) {
        int d1 = j1 + j2 - j3 - k, d2 = j1 - m1 - k, d3 = j2 + m2 - k;
        int d4 = j3 - j2 + m1 + k, d5 = j3 - j1 - m2 + k;
        if (d1 < 0 || d2 < 0 || d3 < 0 || d4 < 0 || d5 < 0) continue;
        double den = cfact(k) * cfact(d1) * cfact(d2) * cfact(d3) * cfact(d4) * cfact(d5);
        s += ((k & 1) ? -1.0 : 1.0) / den;
    }
    return pref * s;
}

struct CPX { double re, im; };
__host__ __device__ constexpr CPX cmulc(CPX a, CPX b) {
    return CPX{a.re * b.re - a.im * b.im, a.re * b.im + a.im * b.re};
}
__host__ __device__ constexpr CPX Uent(int l, int mr, int mc) {
    (void)l;
    double is2 = 1.0 / csqrt_(2.0);
    if (mr > 0) {
        if (mc == mr)  return CPX{((mr & 1) ? -1.0 : 1.0) * is2, 0.0};
        if (mc == -mr) return CPX{is2, 0.0};
    } else if (mr == 0) {
        if (mc == 0) return CPX{1.0, 0.0};
    } else {
        int mu = -mr;
        if (mc == mr) return CPX{0.0, is2};
        if (mc == mu) return CPX{0.0, -((mu & 1) ? -1.0 : 1.0) * is2};
    }
    return CPX{0.0, 0.0};
}

__host__ __device__ constexpr double real_cg(int l1, int l2, int l3, int a, int b, int c) {
    int m1 = a - l1, m2 = b - l2, m3 = c - l3;
    double re = 0.0, im = 0.0;
    for (int sx = 0; sx < 2; ++sx) {
        if (sx && m1 == 0) continue;
        int x = sx ? -m1 : m1;
        CPX u1 = Uent(l1, m1, x); u1.im = -u1.im;
        for (int sy = 0; sy < 2; ++sy) {
            if (sy && m2 == 0) continue;
            int y = sy ? -m2 : m2;
            CPX u2 = Uent(l2, m2, y); u2.im = -u2.im;
            for (int sz = 0; sz < 2; ++sz) {
                if (sz && m3 == 0) continue;
                int z = sz ? -m3 : m3;
                CPX u3 = Uent(l3, m3, z);
                double cg = cg_c(l1, x, l2, y, l3, z);
                if (cg == 0.0) continue;
                CPX t = cmulc(cmulc(u1, u2), u3);
                re += t.re * cg;
                im += t.im * cg;
            }
        }
    }
    return ((l1 + l2 + l3) & 1) ? im : re;
}

// Path table, same enumeration order as reference _build_paths()
__host__ __device__ constexpr int PL1[NPATHS] = {0,0,0,1,1,1,1,1,1,1,2,2,2,2,2,2,2,2,2};
__host__ __device__ constexpr int PL2[NPATHS] = {0,1,2,0,1,1,1,2,2,2,0,1,1,1,2,2,2,2,2};
__host__ __device__ constexpr int PL3[NPATHS] = {0,1,2,1,0,1,2,1,2,3,2,1,2,3,0,1,2,3,4};

template <int I> struct IC { static constexpr int v = I; };
template <int I, int N, class F>
__device__ __forceinline__ void sfor(F&& f) {
    if constexpr (I < N) {
        f(IC<I>{});
        sfor<I + 1, N>(f);
    }
}

__device__ __forceinline__ float wsum(float v) {
    v += __shfl_xor_sync(0xffffffffu, v, 16);
    v += __shfl_xor_sync(0xffffffffu, v, 8);
    v += __shfl_xor_sync(0xffffffffu, v, 4);
    v += __shfl_xor_sync(0xffffffffu, v, 2);
    v += __shfl_xor_sync(0xffffffffu, v, 1);
    return v;
}

// packed f32x2 fma (sm_103): acc = a*b + acc, lanes independent
__device__ __forceinline__ void ffma2(unsigned long long& acc,
                                      unsigned long long a, unsigned long long b) {
    asm("fma.rn.f32x2 %0, %1, %2, %0;" : "+l"(acc) : "l"(a), "l"(b));
}
__device__ __forceinline__ unsigned long long pk2(float lo, float hi) {
    unsigned long long r;
    asm("mov.b64 %0, {%1, %2};" : "=l"(r) : "f"(lo), "f"(hi));
    return r;
}
__device__ __forceinline__ float upk_sum(unsigned long long v) {
    float lo, hi;
    asm("mov.b64 {%0, %1}, %2;" : "=f"(lo), "=f"(hi) : "l"(v));
    return lo + hi;
}

// ============================================================================
// Kernel 1: per-atom B = A @ W1.  warp = row, W1 column resident in registers.
// ============================================================================
__global__ void __launch_bounds__(128) atom_dense_kernel(
    const float* __restrict__ A, const float* __restrict__ W1, int n_rows) {
    const int lane = threadIdx.x & 31;
    float wcol[32];
#pragma unroll
    for (int g = 0; g < 32; ++g) wcol[g] = W1[g * 32 + lane];
    const int wid = (blockIdx.x * blockDim.x + threadIdx.x) >> 5;
    const int nw = (gridDim.x * blockDim.x) >> 5;
    for (int row = wid; row < n_rows; row += nw) {
        const float4* ar = (const float4*)(A + (size_t)row * 32);
        float acc = 0.f;
#pragma unroll
        for (int q = 0; q < 8; ++q) {
            float4 v = ar[q];
            acc = fmaf(v.x, wcol[4 * q + 0], acc);
            acc = fmaf(v.y, wcol[4 * q + 1], acc);
            acc = fmaf(v.z, wcol[4 * q + 2], acc);
            acc = fmaf(v.w, wcol[4 * q + 3], acc);
        }
        g_B[(size_t)row * 32 + lane] = acc;
    }
}

// ============================================================================
// Kernel 2: fused per-edge pipeline. warp = edge, lane = feature.
// R7 skeleton (low live state, per-(par,l3) stores) + f32x2 dense2.
// ============================================================================
__global__ void __launch_bounds__(128, 4) edge_kernel(
    const int* __restrict__ nbr, const float* __restrict__ disp,
    const float* __restrict__ b1, const float* __restrict__ lng,
    const float* __restrict__ lnb, const float* __restrict__ W2,
    const float* __restrict__ b2, const float* __restrict__ Wb,
    const float* __restrict__ bbv, const float* __restrict__ tpw_g,
    float* __restrict__ out, int E) {
    __shared__ __align__(16) float s_wb[1024];         // Wb[k][g]
    __shared__ __align__(16) float s_tpw[NPATHS * 32]; // tp_w[p][g]
    __shared__ __align__(16) float s_yg[4][9][32];     // per-warp gated features
    __shared__ __align__(16) float s_rad[4][32];       // per-warp radial basis

    const int lane = threadIdx.x & 31;
    const int wib = threadIdx.x >> 5;

    for (int x = threadIdx.x; x < 1024; x += blockDim.x) s_wb[x] = Wb[x];
    for (int x = threadIdx.x; x < NPATHS * 32; x += blockDim.x) s_tpw[x] = tpw_g[x];
    __syncthreads();

    // W2 column for this lane, packed into f32x2 pairs (features 2k,2k+1)
    unsigned long long w2p[16];
#pragma unroll
    for (int k = 0; k < 16; ++k)
        w2p[k] = pk2(W2[(2 * k) * 32 + lane], W2[(2 * k + 1) * 32 + lane]);

    const float b1v = b1[lane], b2v = b2[lane], bbc = bbv[lane], betav = lnb[lane];
    const float gm0 = lng[lane], gm1 = lng[32 + lane], gm2 = lng[64 + lane];

    const int wid = (blockIdx.x * blockDim.x + threadIdx.x) >> 5;
    const int nw = (gridDim.x * blockDim.x) >> 5;
    const int2* __restrict__ nbr2 = (const int2*)nbr;

    for (int e = wid; e < E; e += nw) {
        const int2 ij = nbr2[e];

        // ---- y0 = B[i] + B[j] (+ b1 on scalar channel) ----
        float y0[9];
#pragma unroll
        for (int m = 0; m < 9; ++m)
            y0[m] = g_B[((size_t)ij.x * 9 + m) * 32 + lane] +
                    g_B[((size_t)ij.y * 9 + m) * 32 + lane];
        y0[0] += b1v;

        // ---- equivariant layernorm ----
        float yg[9];
        {
            float s = y0[0];
            float mu = wsum(s) * (1.f / 32.f);
            float d = s - mu;
            float var = wsum(d * d) * (1.f / 32.f);
            yg[0] = d * rsqrtf(var + 1e-6f) * gm0 + betav;

            float ss1 = y0[1] * y0[1] + y0[2] * y0[2] + y0[3] * y0[3];
            float inv1 = gm1 * rsqrtf(wsum(ss1) * (1.f / 96.f) + 1e-6f);
            yg[1] = y0[1] * inv1; yg[2] = y0[2] * inv1; yg[3] = y0[3] * inv1;

            float ss2 = y0[4] * y0[4] + y0[5] * y0[5] + y0[6] * y0[6] +
                        y0[7] * y0[7] + y0[8] * y0[8];
            float inv2 = gm2 * rsqrtf(wsum(ss2) * (1.f / 160.f) + 1e-6f);
#pragma unroll
            for (int m = 4; m < 9; ++m) yg[m] = y0[m] * inv2;
        }

        // ---- mish gate (fast-math) ----
        {
            float s = yg[0];
            float ea = __expf(-fabsf(s));
            float sp = fmaxf(s, 0.f) + __logf(1.f + ea);
            float E2 = __expf(-2.f * sp);
            float th = __fdividef(1.f - E2, 1.f + E2);
            float i1 = __fdividef(1.f, 1.f + ea);
            float sig = (s >= 0.f) ? i1 : 1.f - i1;
            yg[0] = s * th;
            float dg = th + s * (1.f - th * th) * sig;
#pragma unroll
            for (int m = 1; m < 9; ++m) yg[m] *= dg;
        }

        // ---- bond basis radial part (per-lane: one exp per warp) ----
        float dx = disp[3 * e], dy = disp[3 * e + 1], dz = disp[3 * e + 2];
        float r = sqrtf(dx * dx + dy * dy + dz * dz);
        float rinv = __fdividef(1.f, fmaxf(r, 1e-12f));
        float ux = dx * rinv, uy = dy * rinv, uz = dz * rinv;

        float ck = (5.0f / 31.0f) * (float)lane;                // linspace(0,5,32)
        float dr = r - ck;
        float cut = (r < 5.f) ? 0.5f * (__cosf(r * 0.6283185307179586f) + 1.f) : 0.f;
        float rad = __expf(-20.48f * dr * dr) * cut;            // gamma=0.5*(32/5)^2

        // ---- stage to smem (ends prior-iteration reads first) ----
        __syncwarp();
#pragma unroll
        for (int m = 0; m < 9; ++m) s_yg[wib][m][lane] = yg[m];
        s_rad[wib][lane] = rad;
        __syncwarp();

        // ---- radW = rad @ Wb  (uniform LDS.128 of rad + per-lane Wb column) ----
        float radW = 0.f;
        {
            const float4* rq = (const float4*)s_rad[wib];
#pragma unroll
            for (int q = 0; q < 8; ++q) {
                float4 rv = rq[q];
                radW = fmaf(rv.x, s_wb[(4 * q + 0) * 32 + lane], radW);
                radW = fmaf(rv.y, s_wb[(4 * q + 1) * 32 + lane], radW);
                radW = fmaf(rv.z, s_wb[(4 * q + 2) * 32 + lane], radW);
                radW = fmaf(rv.w, s_wb[(4 * q + 3) * 32 + lane], radW);
            }
        }
        const float s3 = 1.7320508075688772f;
        float av[9];
        av[0] = radW + bbc;
        av[1] = uy * radW; av[2] = uz * radW; av[3] = ux * radW;
        av[4] = s3 * ux * uy * radW;
        av[5] = s3 * uy * uz * radW;
        av[6] = 0.5f * (3.f * uz * uz - 1.f) * radW;
        av[7] = s3 * ux * uz * radW;
        av[8] = 0.5f * s3 * (ux * ux - uy * uy) * radW;

        // ---- dense2 via uniform LDS.128 + packed f32x2 FMA ----
        float y2[9];
        {
            const ulonglong2* yq = (const ulonglong2*)&s_yg[wib][0][0];
            sfor<0, 9>([&](auto M) {
                constexpr int m = decltype(M)::v;
                unsigned long long acc = 0ull;
#pragma unroll
                for (int q = 0; q < 8; ++q) {
                    ulonglong2 v = yq[m * 8 + q];   // yg[m][4q..4q+3]
                    ffma2(acc, v.x, w2p[2 * q]);
                    ffma2(acc, v.y, w2p[2 * q + 1]);
                }
                y2[m] = upk_sum(acc);
            });
        }
        y2[0] += b2v;
#pragma unroll
        for (int m = 0; m < 9; ++m) y2[m] += y0[m];

        // ---- tensor product per (parity, l3) block; store immediately ----
        float* ob = out + (size_t)e * 1600 + lane;

        auto do_group = [&](auto PARc, auto L3c) {
            constexpr int PAR = decltype(PARc)::v;
            constexpr int L3 = decltype(L3c)::v;
            float acc[2 * L3 + 1];
#pragma unroll
            for (int c = 0; c < 2 * L3 + 1; ++c) acc[c] = 0.f;
            sfor<0, NPATHS>([&](auto P) {
                constexpr int p = decltype(P)::v;
                constexpr int l1 = PL1[p], l2 = PL2[p], l3 = PL3[p];
                constexpr int par = (l1 + l2 + l3) & 1;
                if constexpr (l3 == L3 && par == PAR) {
                    float tw = s_tpw[p * 32 + lane];
                    sfor<0, 2 * l1 + 1>([&](auto Ai) {
                        constexpr int aI = decltype(Ai)::v;
                        float ta = av[l1 * l1 + aI] * tw;
                        sfor<0, 2 * l2 + 1>([&](auto Bi) {
                            constexpr int bI = decltype(Bi)::v;
                            float t = ta * y2[l2 * l2 + bI];
                            sfor<0, 2 * l3 + 1>([&](auto Ci) {
                                constexpr int cI = decltype(Ci)::v;
                                constexpr float cf = (float)real_cg(l1, l2, l3, aI, bI, cI);
                                if constexpr (cf > 1e-7f || cf < -1e-7f)
                                    acc[cI] = fmaf(cf, t, acc[cI]);
                            });
                        });
                    });
                }
            });
            float* og = ob + (PAR * 25 + L3 * L3) * 32;
#pragma unroll
            for (int c = 0; c < 2 * L3 + 1; ++c) og[c * 32] = acc[c];
        };

        do_group(IC<0>{}, IC<0>{});
        do_group(IC<0>{}, IC<1>{});
        do_group(IC<0>{}, IC<2>{});
        do_group(IC<0>{}, IC<3>{});
        do_group(IC<0>{}, IC<4>{});
        do_group(IC<1>{}, IC<1>{});
        do_group(IC<1>{}, IC<2>{});
        do_group(IC<1>{}, IC<3>{});

        // structurally-zero output blocks: (par=1, l3=0) and (par=1, l3=4)
        ob[(25 + 0) * 32] = 0.f;
#pragma unroll
        for (int c = 16; c < 25; ++c) ob[(25 + c) * 32] = 0.f;
    }
}

// ============================================================================
// Launch
// ============================================================================
extern "C" void kernel_launch(void* const* d_in, const int* in_sizes, int n_in,
                              void* d_out, int out_size) {
    const float* A    = (const float*)d_in[0];
    const int*   nbr  = (const int*)d_in[1];
    const float* disp = (const float*)d_in[2];
    const float* W1   = (const float*)d_in[3];
    const float* b1   = (const float*)d_in[4];
    const float* lng  = (const float*)d_in[5];
    const float* lnb  = (const float*)d_in[6];
    const float* W2   = (const float*)d_in[7];
    const float* b2   = (const float*)d_in[8];
    const float* Wb   = (const float*)d_in[9];
    const float* bb   = (const float*)d_in[10];
    const float* tpw  = (const float*)d_in[11];
    float* out = (float*)d_out;

    int n_atoms = in_sizes[0] / (9 * NFEAT);
    int E = in_sizes[1] / 2;

    atom_dense_kernel<<<592, 128>>>(A, W1, n_atoms * 9);
    edge_kernel<<<592, 128>>>(nbr, disp, b1, lng, lnb, W2, b2, Wb, bb, tpw, out, E);
    (void)n_in; (void)out_size;
}

// round 10
// speedup vs baseline: 1.2727x; 1.1017x over previous
#include <cuda_runtime.h>

// ============================================================================
// Problem constants
// ============================================================================
#define NFEAT 32
#define MAX_ATOMS 10000
#define NPATHS 19

// Scratch: per-atom B = A @ W1   (10000 * 9 * 32 floats)
__device__ float g_B[MAX_ATOMS * 9 * NFEAT];

// ============================================================================
// constexpr math (compile-time): factorial, sqrt, exp
// ============================================================================
__host__ __device__ constexpr double cfact(int n) {
    double r = 1.0;
    for (int i = 2; i <= n; ++i) r *= (double)i;
    return r;
}
__host__ __device__ constexpr double csqrt_(double x) {
    if (x <= 0.0) return 0.0;
    double g = x < 1.0 ? 1.0 : x;
    for (int i = 0; i < 80; ++i) g = 0.5 * (g + x / g);
    return g;
}
__host__ __device__ constexpr double cexp_(double x) {
    // exp(x) = (exp(x/1024))^1024, series for the small argument
    double y = x * (1.0 / 1024.0);
    double s = 1.0 + y + y * y / 2.0 + y * y * y / 6.0 + y * y * y * y / 24.0 +
               y * y * y * y * y / 120.0 + y * y * y * y * y * y / 720.0;
    for (int i = 0; i < 10; ++i) s = s * s;
    return s;
}
__host__ __device__ constexpr int iabs_(int x) { return x < 0 ? -x : x; }

// ============================================================================
// constexpr Clebsch-Gordan machinery — bit-faithful port of the reference
// (_cg_complex, _U, _real_cg); every coefficient becomes an FFMA immediate.
// ============================================================================
__host__ __device__ constexpr double cg_c(int j1, int m1, int j2, int m2, int j3, int m3) {
    if (m1 + m2 != m3) return 0.0;
    if (j3 < iabs_(j1 - j2) || j3 > j1 + j2) return 0.0;
    if (iabs_(m1) > j1 || iabs_(m2) > j2 || iabs_(m3) > j3) return 0.0;
    double pref = csqrt_((2.0 * j3 + 1.0) * cfact(j3 + j1 - j2) * cfact(j3 - j1 + j2) *
                         cfact(j1 + j2 - j3) / cfact(j1 + j2 + j3 + 1));
    pref *= csqrt_(cfact(j3 + m3) * cfact(j3 - m3) * cfact(j1 - m1) * cfact(j1 + m1) *
                   cfact(j2 - m2) * cfact(j2 + m2));
    double s = 0.0;
    for (int k = 0; k <= j1 + j2 - j3; ++k) {
        int d1 = j1 + j2 - j3 - k, d2 = j1 - m1 - k, d3 = j2 + m2 - k;
        int d4 = j3 - j2 + m1 + k, d5 = j3 - j1 - m2 + k;
        if (d1 < 0 || d2 < 0 || d3 < 0 || d4 < 0 || d5 < 0) continue;
        double den = cfact(k) * cfact(d1) * cfact(d2) * cfact(d3) * cfact(d4) * cfact(d5);
        s += ((k & 1) ? -1.0 : 1.0) / den;
    }
    return pref * s;
}

struct CPX { double re, im; };
__host__ __device__ constexpr CPX cmulc(CPX a, CPX b) {
    return CPX{a.re * b.re - a.im * b.im, a.re * b.im + a.im * b.re};
}
__host__ __device__ constexpr CPX Uent(int l, int mr, int mc) {
    (void)l;
    double is2 = 1.0 / csqrt_(2.0);
    if (mr > 0) {
        if (mc == mr)  return CPX{((mr & 1) ? -1.0 : 1.0) * is2, 0.0};
        if (mc == -mr) return CPX{is2, 0.0};
    } else if (mr == 0) {
        if (mc == 0) return CPX{1.0, 0.0};
    } else {
        int mu = -mr;
        if (mc == mr) return CPX{0.0, is2};
        if (mc == mu) return CPX{0.0, -((mu & 1) ? -1.0 : 1.0) * is2};
    }
    return CPX{0.0, 0.0};
}

__host__ __device__ constexpr double real_cg(int l1, int l2, int l3, int a, int b, int c) {
    int m1 = a - l1, m2 = b - l2, m3 = c - l3;
    double re = 0.0, im = 0.0;
    for (int sx = 0; sx < 2; ++sx) {
        if (sx && m1 == 0) continue;
        int x = sx ? -m1 : m1;
        CPX u1 = Uent(l1, m1, x); u1.im = -u1.im;
        for (int sy = 0; sy < 2; ++sy) {
            if (sy && m2 == 0) continue;
            int y = sy ? -m2 : m2;
            CPX u2 = Uent(l2, m2, y); u2.im = -u2.im;
            for (int sz = 0; sz < 2; ++sz) {
                if (sz && m3 == 0) continue;
                int z = sz ? -m3 : m3;
                CPX u3 = Uent(l3, m3, z);
                double cg = cg_c(l1, x, l2, y, l3, z);
                if (cg == 0.0) continue;
                CPX t = cmulc(cmulc(u1, u2), u3);
                re += t.re * cg;
                im += t.im * cg;
            }
        }
    }
    return ((l1 + l2 + l3) & 1) ? im : re;
}

// Path table, same enumeration order as reference _build_paths()
__host__ __device__ constexpr int PL1[NPATHS] = {0,0,0,1,1,1,1,1,1,1,2,2,2,2,2,2,2,2,2};
__host__ __device__ constexpr int PL2[NPATHS] = {0,1,2,0,1,1,1,2,2,2,0,1,1,1,2,2,2,2,2};
__host__ __device__ constexpr int PL3[NPATHS] = {0,1,2,1,0,1,2,1,2,3,2,1,2,3,0,1,2,3,4};

template <int I> struct IC { static constexpr int v = I; };
template <int I, int N, class F>
__device__ __forceinline__ void sfor(F&& f) {
    if constexpr (I < N) {
        f(IC<I>{});
        sfor<I + 1, N>(f);
    }
}

__device__ __forceinline__ float wsum(float v) {
    v += __shfl_xor_sync(0xffffffffu, v, 16);
    v += __shfl_xor_sync(0xffffffffu, v, 8);
    v += __shfl_xor_sync(0xffffffffu, v, 4);
    v += __shfl_xor_sync(0xffffffffu, v, 2);
    v += __shfl_xor_sync(0xffffffffu, v, 1);
    return v;
}

// packed f32x2 fma (sm_103): acc = a*b + acc, lanes independent
__device__ __forceinline__ void ffma2(unsigned long long& acc,
                                      unsigned long long a, unsigned long long b) {
    asm("fma.rn.f32x2 %0, %1, %2, %0;" : "+l"(acc) : "l"(a), "l"(b));
}
__device__ __forceinline__ unsigned long long pk2(float lo, float hi) {
    unsigned long long r;
    asm("mov.b64 %0, {%1, %2};" : "=l"(r) : "f"(lo), "f"(hi));
    return r;
}
__device__ __forceinline__ float upk_sum(unsigned long long v) {
    float lo, hi;
    asm("mov.b64 {%0, %1}, %2;" : "=f"(lo), "=f"(hi) : "l"(v));
    return lo + hi;
}

// Radial basis constants
#define RB_GAMMA 20.48f
#define RB_DELTA (5.0f / 31.0f)
// 2*gamma*delta
#define RB_2GD 6.6064516129032258f
// gamma*delta^2 (double, for compile-time H table)
#define RB_GDD 0.5327783558792925

// ============================================================================
// Kernel 1: per-atom B = A @ W1.  warp = row, W1 column resident in registers.
// ============================================================================
__global__ void __launch_bounds__(128) atom_dense_kernel(
    const float* __restrict__ A, const float* __restrict__ W1, int n_rows) {
    const int lane = threadIdx.x & 31;
    float wcol[32];
#pragma unroll
    for (int g = 0; g < 32; ++g) wcol[g] = W1[g * 32 + lane];
    const int wid = (blockIdx.x * blockDim.x + threadIdx.x) >> 5;
    const int nw = (gridDim.x * blockDim.x) >> 5;
    for (int row = wid; row < n_rows; row += nw) {
        const float4* ar = (const float4*)(A + (size_t)row * 32);
        float acc = 0.f;
#pragma unroll
        for (int q = 0; q < 8; ++q) {
            float4 v = ar[q];
            acc = fmaf(v.x, wcol[4 * q + 0], acc);
            acc = fmaf(v.y, wcol[4 * q + 1], acc);
            acc = fmaf(v.z, wcol[4 * q + 2], acc);
            acc = fmaf(v.w, wcol[4 * q + 3], acc);
        }
        g_B[(size_t)row * 32 + lane] = acc;
    }
}

// ============================================================================
// Kernel 2: fused per-edge pipeline. warp = edge, lane = feature.
// ============================================================================
__global__ void __launch_bounds__(128, 5) edge_kernel(
    const int* __restrict__ nbr, const float* __restrict__ disp,
    const float* __restrict__ b1, const float* __restrict__ lng,
    const float* __restrict__ lnb, const float* __restrict__ W2,
    const float* __restrict__ b2, const float* __restrict__ Wb,
    const float* __restrict__ bbv, const float* __restrict__ tpw_g,
    float* __restrict__ out, int E) {
    // Wb padded: rows -6..37 (index +6), zero rows outside [0,32)
    __shared__ __align__(16) float s_wbp[44 * 32];
    __shared__ __align__(16) float s_tpw[NPATHS * 32]; // tp_w[p][g]
    __shared__ __align__(16) float s_yg[4][9][32];     // per-warp gated features

    const int lane = threadIdx.x & 31;
    const int wib = threadIdx.x >> 5;

    for (int x = threadIdx.x; x < 44 * 32; x += blockDim.x) {
        int row = (x >> 5) - 6;
        s_wbp[x] = (row >= 0 && row < 32) ? Wb[row * 32 + (x & 31)] : 0.f;
    }
    for (int x = threadIdx.x; x < NPATHS * 32; x += blockDim.x) s_tpw[x] = tpw_g[x];
    __syncthreads();

    // W2 column for this lane, packed into f32x2 pairs (features 2k,2k+1)
    unsigned long long w2p[16];
#pragma unroll
    for (int k = 0; k < 16; ++k)
        w2p[k] = pk2(W2[(2 * k) * 32 + lane], W2[(2 * k + 1) * 32 + lane]);

    const float b1v = b1[lane], b2v = b2[lane], bbc = bbv[lane], betav = lnb[lane];
    const float gm0 = lng[lane], gm1 = lng[32 + lane], gm2 = lng[64 + lane];

    const int wid = (blockIdx.x * blockDim.x + threadIdx.x) >> 5;
    const int nw = (gridDim.x * blockDim.x) >> 5;
    const int2* __restrict__ nbr2 = (const int2*)nbr;

    for (int e = wid; e < E; e += nw) {
        const int2 ij = nbr2[e];

        // ---- y0 = B[i] + B[j] (+ b1 on scalar channel) ----
        float y0[9];
#pragma unroll
        for (int m = 0; m < 9; ++m)
            y0[m] = g_B[((size_t)ij.x * 9 + m) * 32 + lane] +
                    g_B[((size_t)ij.y * 9 + m) * 32 + lane];
        y0[0] += b1v;

        // ---- equivariant layernorm ----
        float yg[9];
        {
            float s = y0[0];
            float mu = wsum(s) * (1.f / 32.f);
            float d = s - mu;
            float var = wsum(d * d) * (1.f / 32.f);
            yg[0] = d * rsqrtf(var + 1e-6f) * gm0 + betav;

            float ss1 = y0[1] * y0[1] + y0[2] * y0[2] + y0[3] * y0[3];
            float inv1 = gm1 * rsqrtf(wsum(ss1) * (1.f / 96.f) + 1e-6f);
            yg[1] = y0[1] * inv1; yg[2] = y0[2] * inv1; yg[3] = y0[3] * inv1;

            float ss2 = y0[4] * y0[4] + y0[5] * y0[5] + y0[6] * y0[6] +
                        y0[7] * y0[7] + y0[8] * y0[8];
            float inv2 = gm2 * rsqrtf(wsum(ss2) * (1.f / 160.f) + 1e-6f);
#pragma unroll
            for (int m = 4; m < 9; ++m) yg[m] = y0[m] * inv2;
        }

        // ---- mish gate (fast-math) ----
        {
            float s = yg[0];
            float ea = __expf(-fabsf(s));
            float sp = fmaxf(s, 0.f) + __logf(1.f + ea);
            float E2 = __expf(-2.f * sp);
            float th = __fdividef(1.f - E2, 1.f + E2);
            float i1 = __fdividef(1.f, 1.f + ea);
            float sig = (s >= 0.f) ? i1 : 1.f - i1;
            yg[0] = s * th;
            float dg = th + s * (1.f - th * th) * sig;
#pragma unroll
            for (int m = 1; m < 9; ++m) yg[m] *= dg;
        }

        // ---- stage yg to smem for broadcast dense2 ----
        __syncwarp();
#pragma unroll
        for (int m = 0; m < 9; ++m) s_yg[wib][m][lane] = yg[m];
        __syncwarp();

        // ---- bond geometry ----
        float dx = disp[3 * e], dy = disp[3 * e + 1], dz = disp[3 * e + 2];
        float r = sqrtf(dx * dx + dy * dy + dz * dz);
        float rinv = __fdividef(1.f, fmaxf(r, 1e-12f));
        float ux = dx * rinv, uy = dy * rinv, uz = dz * rinv;

        // ---- radW[g] = sum_k rad[k]*Wb[k][g] via 13-tap geometric window ----
        // rad[kc+D] = rad_c * beta^D * H[D], H[D]=exp(-gamma*delta^2*D^2) imm.
        float radW = 0.f;
        if (r < 5.f) {                                   // warp-uniform branch
            int kc = __float2int_rn(r * (31.0f / 5.0f));
            float t = r - (float)kc * RB_DELTA;          // |t| <= delta/2
            float rad_c = __expf(-RB_GAMMA * t * t);
            float beta = __expf(RB_2GD * t);
            float b2_ = beta * beta, b4 = b2_ * b2_;
            float bp = __fdividef(1.f, b4 * b2_);        // beta^-6
            float acc = 0.f;
            const float* wrow = s_wbp + (kc * 32 + lane);  // D=-6 row is +0
            sfor<0, 13>([&](auto Dc) {
                constexpr int D = decltype(Dc)::v - 6;
                constexpr float H = (float)cexp_(-RB_GDD * (double)(D * D));
                acc = fmaf(bp * H, wrow[(D + 6) * 32], acc);
                bp *= beta;
            });
            float cut = 0.5f * (__cosf(r * 0.6283185307179586f) + 1.f);
            radW = rad_c * cut * acc;
        }

        const float s3 = 1.7320508075688772f;
        float av[9];
        av[0] = radW + bbc;
        av[1] = uy * radW; av[2] = uz * radW; av[3] = ux * radW;
        av[4] = s3 * ux * uy * radW;
        av[5] = s3 * uy * uz * radW;
        av[6] = 0.5f * (3.f * uz * uz - 1.f) * radW;
        av[7] = s3 * ux * uz * radW;
        av[8] = 0.5f * s3 * (ux * ux - uy * uy) * radW;

        // ---- dense2 via uniform LDS.128 + packed f32x2 FMA ----
        float y2[9];
        {
            const ulonglong2* yq = (const ulonglong2*)&s_yg[wib][0][0];
            sfor<0, 9>([&](auto M) {
                constexpr int m = decltype(M)::v;
                unsigned long long acc = 0ull;
#pragma unroll
                for (int q = 0; q < 8; ++q) {
                    ulonglong2 v = yq[m * 8 + q];   // yg[m][4q..4q+3]
                    ffma2(acc, v.x, w2p[2 * q]);
                    ffma2(acc, v.y, w2p[2 * q + 1]);
                }
                y2[m] = upk_sum(acc);
            });
        }
        y2[0] += b2v;
#pragma unroll
        for (int m = 0; m < 9; ++m) y2[m] += y0[m];

        // ---- tensor product per (parity, l3) block; store immediately ----
        float* ob = out + (size_t)e * 1600 + lane;

        auto do_group = [&](auto PARc, auto L3c) {
            constexpr int PAR = decltype(PARc)::v;
            constexpr int L3 = decltype(L3c)::v;
            float acc[2 * L3 + 1];
#pragma unroll
            for (int c = 0; c < 2 * L3 + 1; ++c) acc[c] = 0.f;
            sfor<0, NPATHS>([&](auto P) {
                constexpr int p = decltype(P)::v;
                constexpr int l1 = PL1[p], l2 = PL2[p], l3 = PL3[p];
                constexpr int par = (l1 + l2 + l3) & 1;
                if constexpr (l3 == L3 && par == PAR) {
                    float tw = s_tpw[p * 32 + lane];
                    sfor<0, 2 * l1 + 1>([&](auto Ai) {
                        constexpr int aI = decltype(Ai)::v;
                        float ta = av[l1 * l1 + aI] * tw;
                        sfor<0, 2 * l2 + 1>([&](auto Bi) {
                            constexpr int bI = decltype(Bi)::v;
                            float t = ta * y2[l2 * l2 + bI];
                            sfor<0, 2 * l3 + 1>([&](auto Ci) {
                                constexpr int cI = decltype(Ci)::v;
                                constexpr float cf = (float)real_cg(l1, l2, l3, aI, bI, cI);
                                if constexpr (cf > 1e-7f || cf < -1e-7f)
                                    acc[cI] = fmaf(cf, t, acc[cI]);
                            });
                        });
                    });
                }
            });
            float* og = ob + (PAR * 25 + L3 * L3) * 32;
#pragma unroll
            for (int c = 0; c < 2 * L3 + 1; ++c) __stcs(og + c * 32, acc[c]);
        };

        do_group(IC<0>{}, IC<0>{});
        do_group(IC<0>{}, IC<1>{});
        do_group(IC<0>{}, IC<2>{});
        do_group(IC<0>{}, IC<3>{});
        do_group(IC<0>{}, IC<4>{});
        do_group(IC<1>{}, IC<1>{});
        do_group(IC<1>{}, IC<2>{});
        do_group(IC<1>{}, IC<3>{});

        // structurally-zero output blocks: (par=1, l3=0) and (par=1, l3=4)
        __stcs(ob + (25 + 0) * 32, 0.f);
#pragma unroll
        for (int c = 16; c < 25; ++c) __stcs(ob + (25 + c) * 32, 0.f);
    }
}

// ============================================================================
// Launch
// ============================================================================
extern "C" void kernel_launch(void* const* d_in, const int* in_sizes, int n_in,
                              void* d_out, int out_size) {
    const float* A    = (const float*)d_in[0];
    const int*   nbr  = (const int*)d_in[1];
    const float* disp = (const float*)d_in[2];
    const float* W1   = (const float*)d_in[3];
    const float* b1   = (const float*)d_in[4];
    const float* lng  = (const float*)d_in[5];
    const float* lnb  = (const float*)d_in[6];
    const float* W2   = (const float*)d_in[7];
    const float* b2   = (const float*)d_in[8];
    const float* Wb   = (const float*)d_in[9];
    const float* bb   = (const float*)d_in[10];
    const float* tpw  = (const float*)d_in[11];
    float* out = (float*)d_out;

    int n_atoms = in_sizes[0] / (9 * NFEAT);
    int E = in_sizes[1] / 2;

    atom_dense_kernel<<<592, 128>>>(A, W1, n_atoms * 9);
    edge_kernel<<<740, 128>>>(nbr, disp, b1, lng, lnb, W2, b2, Wb, bb, tpw, out, E);
    (void)n_in; (void)out_size;
}